// round 13
// baseline (speedup 1.0000x reference)
#include <cuda_runtime.h>
#include <math.h>

#define EPSF 1e-7f

// -------- device scratch (static, allowed) --------
__device__ float g_Wc[784 * 64];     // W_in @ W_tan
__device__ float g_bc[64];           // b_in @ W_tan + b_tan
__device__ float g_W1e0[64 * 56];    // R0^T @ t0_w1
__device__ float g_W1e1[48 * 40];    // R1^T @ t1_w1

// ============================================================
// P1: fold input projection:  Wc = W_in @ W_tan,  bc = b_in@W_tan + b_tan
// ============================================================
__global__ void precompute_wc(const float* __restrict__ W_in,
                              const float* __restrict__ b_in,
                              const float* __restrict__ W_tan,
                              const float* __restrict__ b_tan) {
    int idx = blockIdx.x * blockDim.x + threadIdx.x;
    if (idx < 784 * 64) {
        int i = idx >> 6, j = idx & 63;
        float s = 0.f;
        #pragma unroll 8
        for (int k = 0; k < 128; k++)
            s = fmaf(W_in[i * 128 + k], W_tan[k * 64 + j], s);
        g_Wc[idx] = s;
    } else if (idx < 784 * 64 + 64) {
        int j = idx - 784 * 64;
        float s = b_tan[j];
        for (int k = 0; k < 128; k++)
            s = fmaf(b_in[k], W_tan[k * 64 + j], s);
        g_bc[j] = s;
    }
}

// ============================================================
// P2: R = expm(A - A^T) via scaling(1/64)+Taylor(9)+squaring(6),
//     then fold W1eff = R^T @ w1. Block 0 -> level0, block 1 -> level1.
// ============================================================
__device__ void bmm_block(const float* Am, const float* Bm, float* Cm,
                          int n, float scale, bool addI) {
    __syncthreads();
    for (int idx = threadIdx.x; idx < n * n; idx += blockDim.x) {
        int i = idx / n, j = idx - i * n;
        float s = 0.f;
        for (int k = 0; k < n; k++)
            s = fmaf(Am[i * n + k], Bm[k * n + j], s);
        s *= scale;
        if (addI && i == j) s += 1.f;
        Cm[idx] = s;
    }
}

__global__ void precompute_rot(const float* __restrict__ A0,
                               const float* __restrict__ A1,
                               const float* __restrict__ w1_0,
                               const float* __restrict__ w1_1) {
    extern __shared__ float sh[];
    float* M  = sh;
    float* T1 = sh + 4096;
    float* T2 = sh + 8192;

    int n, h;
    const float* Ain;
    const float* W1;
    float* outp;
    if (blockIdx.x == 0) { n = 64; h = 56; Ain = A0; W1 = w1_0; outp = g_W1e0; }
    else                 { n = 48; h = 40; Ain = A1; W1 = w1_1; outp = g_W1e1; }

    // M = (A - A^T) / 64
    for (int idx = threadIdx.x; idx < n * n; idx += blockDim.x) {
        int i = idx / n, j = idx - i * n;
        M[idx] = (Ain[i * n + j] - Ain[j * n + i]) * (1.f / 64.f);
    }
    __syncthreads();
    // Horner: T = I + M/9
    for (int idx = threadIdx.x; idx < n * n; idx += blockDim.x) {
        int i = idx / n, j = idx - i * n;
        T1[idx] = M[idx] * (1.f / 9.f) + (i == j ? 1.f : 0.f);
    }
    float* cur = T1;
    float* nxt = T2;
    for (int k = 8; k >= 1; k--) {          // T = I + M*T/k
        bmm_block(M, cur, nxt, n, 1.f / (float)k, true);
        float* t = cur; cur = nxt; nxt = t;
    }
    for (int t = 0; t < 6; t++) {           // 6 squarings (2^6 = 64)
        bmm_block(cur, cur, nxt, n, 1.f, false);
        float* tt = cur; cur = nxt; nxt = tt;
    }
    __syncthreads();
    // fold: out[i][j] = sum_m R[m][i] * w1[m][j]   (= R^T @ w1)
    for (int idx = threadIdx.x; idx < n * h; idx += blockDim.x) {
        int i = idx / h, j = idx - i * h;
        float s = 0.f;
        for (int m = 0; m < n; m++)
            s = fmaf(cur[m * n + i], W1[m * h + j], s);
        outp[idx] = s;
    }
}

// ============================================================
// Per-row scalar gain for one WuBu level:
//   t = v * gain(||v||)  implements scale->expmap0->projx->logmap0->unscale
// ============================================================
__device__ __forceinline__ float level_gain(float nv, float sqc, float s) {
    float un = fmaxf(s * nv, EPSF);
    float z  = sqc * un;
    float th = tanhf(z);
    float coef1 = s * th / z;                       // xh = coef1 * v
    float xhn   = coef1 * nv;                       // ||xh||
    float maxn  = (1.f - 1e-5f) / sqc;
    float clampP = fminf(1.f, maxn / fmaxf(xhn, EPSF));
    float xn2 = fmaxf(xhn * clampP, EPSF);
    float arg = fminf(sqc * xn2, 1.f - 1e-7f);
    float at  = atanhf(arg);
    return coef1 * clampP * at / (sqc * xn2) / (s + EPSF);
}

// ============================================================
// Main fused kernel: GEMM1 (128x64, K=784) + 3 levels + 2 MLPs + output head
// ============================================================
// smem layout (floats):
//  A      [128*65] = 8320     (v / t buffers)
//  Bb     [128*57] = 7296     (h buffers; also x_tile[128*17] + w_tile[16*64] during GEMM)
//  W1e0s  3584, W20s 2688, W1e1s 1920, W21s 1280, Wos 1440, biases 176
#define SMEM_FLOATS 26704

__global__ __launch_bounds__(256, 2)
void fused_kernel(const float* __restrict__ x,
                  const float* __restrict__ s0p, const float* __restrict__ s1p,
                  const float* __restrict__ s2p,
                  const float* __restrict__ w2_0, const float* __restrict__ b1_0,
                  const float* __restrict__ b2_0,
                  const float* __restrict__ w2_1, const float* __restrict__ b1_1,
                  const float* __restrict__ b2_1,
                  const float* __restrict__ Wout, const float* __restrict__ bout,
                  float* __restrict__ out, int B) {
    extern __shared__ float sh[];
    float* A     = sh;                 // stride 65
    float* Bb    = sh + 8320;          // stride 57
    float* xT    = Bb;                 // stride 17 (GEMM phase only)
    float* wT    = Bb + 2176;          // 16 x 64   (GEMM phase only)
    float* W1e0s = sh + 15616;
    float* W20s  = sh + 19200;
    float* W1e1s = sh + 21888;
    float* W21s  = sh + 23808;
    float* Wos   = sh + 25088;
    float* b10s  = sh + 26528;
    float* b20s  = sh + 26584;
    float* b11s  = sh + 26632;
    float* b21s  = sh + 26672;

    const int tid = threadIdx.x;
    const int blockRow = blockIdx.x * 128;

    // stage downstream weights into smem (first use is well after several syncs)
    for (int i = tid; i < 3584; i += 256) W1e0s[i] = g_W1e0[i];
    for (int i = tid; i < 2688; i += 256) W20s[i]  = w2_0[i];
    for (int i = tid; i < 1920; i += 256) W1e1s[i] = g_W1e1[i];
    for (int i = tid; i < 1280; i += 256) W21s[i]  = w2_1[i];
    for (int i = tid; i < 1440; i += 256) Wos[i]   = Wout[i];
    if (tid < 56) b10s[tid] = b1_0[tid];
    if (tid < 48) b20s[tid] = b2_0[tid];
    if (tid < 40) b11s[tid] = b1_1[tid];
    if (tid < 32) b21s[tid] = b2_1[tid];

    // ---------------- GEMM1: v[128x64] = x_tile @ Wc ----------------
    const int ty = tid >> 4, tx = tid & 15;
    const int r0 = ty * 8, c0 = tx * 4;
    float acc[8][4];
    #pragma unroll
    for (int i = 0; i < 8; i++)
        #pragma unroll
        for (int j = 0; j < 4; j++) acc[i][j] = 0.f;

    const int lrow = tid >> 1;          // 0..127
    const int lq   = tid & 1;
    const bool rowOK = (blockRow + lrow) < B;
    const float* xrow = x + (size_t)(blockRow + lrow) * 784 + lq * 8;
    const int wk = tid >> 4, wf = tid & 15;

    for (int k0 = 0; k0 < 784; k0 += 16) {
        float4 xa = rowOK ? *(const float4*)(xrow + k0)     : make_float4(0, 0, 0, 0);
        float4 xb = rowOK ? *(const float4*)(xrow + k0 + 4) : make_float4(0, 0, 0, 0);
        float4 wv = *(const float4*)(g_Wc + (k0 + wk) * 64 + wf * 4);
        __syncthreads();  // previous chunk's compute done
        float* xd = xT + lrow * 17 + lq * 8;
        xd[0] = xa.x; xd[1] = xa.y; xd[2] = xa.z; xd[3] = xa.w;
        xd[4] = xb.x; xd[5] = xb.y; xd[6] = xb.z; xd[7] = xb.w;
        *(float4*)(wT + wk * 64 + wf * 4) = wv;
        __syncthreads();
        #pragma unroll
        for (int k = 0; k < 16; k++) {
            float4 bv = *(float4*)(wT + k * 64 + c0);
            #pragma unroll
            for (int i = 0; i < 8; i++) {
                float a = xT[(r0 + i) * 17 + k];
                acc[i][0] = fmaf(a, bv.x, acc[i][0]);
                acc[i][1] = fmaf(a, bv.y, acc[i][1]);
                acc[i][2] = fmaf(a, bv.z, acc[i][2]);
                acc[i][3] = fmaf(a, bv.w, acc[i][3]);
            }
        }
    }

    // bias + level 0 (c=1.0), write t0 -> A
    {
        float4 bc4 = *(const float4*)(g_bc + c0);
        const float s0 = fmaxf(__ldg(s0p), 1e-4f);
        #pragma unroll
        for (int i = 0; i < 8; i++) {
            acc[i][0] += bc4.x; acc[i][1] += bc4.y;
            acc[i][2] += bc4.z; acc[i][3] += bc4.w;
            float p = acc[i][0] * acc[i][0] + acc[i][1] * acc[i][1]
                    + acc[i][2] * acc[i][2] + acc[i][3] * acc[i][3];
            p += __shfl_xor_sync(0xffffffffu, p, 1);
            p += __shfl_xor_sync(0xffffffffu, p, 2);
            p += __shfl_xor_sync(0xffffffffu, p, 4);
            p += __shfl_xor_sync(0xffffffffu, p, 8);
            float g = level_gain(sqrtf(p), 1.0f, s0);   // sqrt(c0)=1
            float* Ar = A + (r0 + i) * 65 + c0;
            Ar[0] = acc[i][0] * g; Ar[1] = acc[i][1] * g;
            Ar[2] = acc[i][2] * g; Ar[3] = acc[i][3] * g;
        }
    }
    __syncthreads();

    // output-head accumulators (2 threads / row, 5 cols each)
    const int orow = tid >> 1;
    const int oc0  = (tid & 1) * 5;
    float oacc[5];
    #pragma unroll
    for (int j = 0; j < 5; j++) oacc[j] = __ldg(bout + oc0 + j);

    const int rg = tid >> 3, cg = tid & 7;
    const int sr = rg * 4;

    // ------ phase 2: h = relu(t0 @ W1e0 + b1_0) [128x56]; oacc += t0 @ Wo[0:64] ------
    {
        float hacc[4][7];
        #pragma unroll
        for (int i = 0; i < 4; i++)
            #pragma unroll
            for (int j = 0; j < 7; j++) hacc[i][j] = b10s[cg * 7 + j];
        #pragma unroll 4
        for (int k = 0; k < 64; k++) {
            float w[7];
            #pragma unroll
            for (int j = 0; j < 7; j++) w[j] = W1e0s[k * 56 + cg * 7 + j];
            #pragma unroll
            for (int i = 0; i < 4; i++) {
                float a = A[(sr + i) * 65 + k];
                #pragma unroll
                for (int j = 0; j < 7; j++) hacc[i][j] = fmaf(a, w[j], hacc[i][j]);
            }
        }
        #pragma unroll
        for (int i = 0; i < 4; i++)
            #pragma unroll
            for (int j = 0; j < 7; j++)
                Bb[(sr + i) * 57 + cg * 7 + j] = fmaxf(hacc[i][j], 0.f);
        #pragma unroll 4
        for (int k = 0; k < 64; k++) {
            float a = A[orow * 65 + k];
            #pragma unroll
            for (int j = 0; j < 5; j++)
                oacc[j] = fmaf(a, Wos[k * 10 + oc0 + j], oacc[j]);
        }
    }
    __syncthreads();

    // ------ phase 3: v1 = h @ w2_0 + b2_0 [128x48]; level1 (c=0.8); t1 -> A ------
    {
        const float s1 = fmaxf(__ldg(s1p), 1e-5f);
        const float sqc1 = sqrtf(0.8f);
        float vacc[4][6];
        #pragma unroll
        for (int i = 0; i < 4; i++)
            #pragma unroll
            for (int j = 0; j < 6; j++) vacc[i][j] = b20s[cg * 6 + j];
        #pragma unroll 4
        for (int k = 0; k < 56; k++) {
            float w[6];
            #pragma unroll
            for (int j = 0; j < 6; j++) w[j] = W20s[k * 48 + cg * 6 + j];
            #pragma unroll
            for (int i = 0; i < 4; i++) {
                float a = Bb[(sr + i) * 57 + k];
                #pragma unroll
                for (int j = 0; j < 6; j++) vacc[i][j] = fmaf(a, w[j], vacc[i][j]);
            }
        }
        #pragma unroll
        for (int i = 0; i < 4; i++) {
            float p = 0.f;
            #pragma unroll
            for (int j = 0; j < 6; j++) p += vacc[i][j] * vacc[i][j];
            p += __shfl_xor_sync(0xffffffffu, p, 1);
            p += __shfl_xor_sync(0xffffffffu, p, 2);
            p += __shfl_xor_sync(0xffffffffu, p, 4);
            float g = level_gain(sqrtf(p), sqc1, s1);
            #pragma unroll
            for (int j = 0; j < 6; j++)
                A[(sr + i) * 65 + cg * 6 + j] = vacc[i][j] * g;
        }
    }
    __syncthreads();

    // ------ phase 4: h2 = relu(t1 @ W1e1 + b1_1) [128x40]; oacc += t1 @ Wo[64:112] ------
    {
        float hacc[4][5];
        #pragma unroll
        for (int i = 0; i < 4; i++)
            #pragma unroll
            for (int j = 0; j < 5; j++) hacc[i][j] = b11s[cg * 5 + j];
        #pragma unroll 4
        for (int k = 0; k < 48; k++) {
            float w[5];
            #pragma unroll
            for (int j = 0; j < 5; j++) w[j] = W1e1s[k * 40 + cg * 5 + j];
            #pragma unroll
            for (int i = 0; i < 4; i++) {
                float a = A[(sr + i) * 65 + k];
                #pragma unroll
                for (int j = 0; j < 5; j++) hacc[i][j] = fmaf(a, w[j], hacc[i][j]);
            }
        }
        #pragma unroll
        for (int i = 0; i < 4; i++)
            #pragma unroll
            for (int j = 0; j < 5; j++)
                Bb[(sr + i) * 57 + cg * 5 + j] = fmaxf(hacc[i][j], 0.f);
        #pragma unroll 4
        for (int k = 0; k < 48; k++) {
            float a = A[orow * 65 + k];
            #pragma unroll
            for (int j = 0; j < 5; j++)
                oacc[j] = fmaf(a, Wos[(64 + k) * 10 + oc0 + j], oacc[j]);
        }
    }
    __syncthreads();

    // ------ phase 5: v2 = h2 @ w2_1 + b2_1 [128x32]; level2 (c=1.2); t2 -> A ------
    {
        const float s2 = fmaxf(__ldg(s2p), 1e-6f);
        const float sqc2 = sqrtf(1.2f);
        float vacc[4][4];
        #pragma unroll
        for (int i = 0; i < 4; i++)
            #pragma unroll
            for (int j = 0; j < 4; j++) vacc[i][j] = b21s[cg * 4 + j];
        #pragma unroll 4
        for (int k = 0; k < 40; k++) {
            float w[4];
            #pragma unroll
            for (int j = 0; j < 4; j++) w[j] = W21s[k * 32 + cg * 4 + j];
            #pragma unroll
            for (int i = 0; i < 4; i++) {
                float a = Bb[(sr + i) * 57 + k];
                #pragma unroll
                for (int j = 0; j < 4; j++) vacc[i][j] = fmaf(a, w[j], vacc[i][j]);
            }
        }
        #pragma unroll
        for (int i = 0; i < 4; i++) {
            float p = 0.f;
            #pragma unroll
            for (int j = 0; j < 4; j++) p += vacc[i][j] * vacc[i][j];
            p += __shfl_xor_sync(0xffffffffu, p, 1);
            p += __shfl_xor_sync(0xffffffffu, p, 2);
            p += __shfl_xor_sync(0xffffffffu, p, 4);
            float g = level_gain(sqrtf(p), sqc2, s2);
            #pragma unroll
            for (int j = 0; j < 4; j++)
                A[(sr + i) * 65 + cg * 4 + j] = vacc[i][j] * g;
        }
    }
    __syncthreads();

    // ------ phase 6: oacc += t2 @ Wo[112:144]; store out ------
    #pragma unroll 4
    for (int k = 0; k < 32; k++) {
        float a = A[orow * 65 + k];
        #pragma unroll
        for (int j = 0; j < 5; j++)
            oacc[j] = fmaf(a, Wos[(112 + k) * 10 + oc0 + j], oacc[j]);
    }
    if (blockRow + orow < B) {
        float* op = out + (size_t)(blockRow + orow) * 10 + oc0;
        #pragma unroll
        for (int j = 0; j < 5; j++) op[j] = oacc[j];
    }
}

// ============================================================
extern "C" void kernel_launch(void* const* d_in, const int* in_sizes, int n_in,
                              void* d_out, int out_size) {
    const float* x     = (const float*)d_in[0];
    const float* W_in  = (const float*)d_in[1];
    const float* b_in  = (const float*)d_in[2];
    const float* W_tan = (const float*)d_in[3];
    const float* b_tan = (const float*)d_in[4];
    const float* s0    = (const float*)d_in[5];
    const float* s1    = (const float*)d_in[6];
    const float* s2    = (const float*)d_in[7];
    // d_in[8] = tp0, d_in[9] = tp1 : boundary side-path, provably unused in output
    const float* A0    = (const float*)d_in[10];
    const float* A1    = (const float*)d_in[11];
    const float* t0_w1 = (const float*)d_in[12];
    const float* t0_b1 = (const float*)d_in[13];
    const float* t0_w2 = (const float*)d_in[14];
    const float* t0_b2 = (const float*)d_in[15];
    const float* t1_w1 = (const float*)d_in[16];
    const float* t1_b1 = (const float*)d_in[17];
    const float* t1_w2 = (const float*)d_in[18];
    const float* t1_b2 = (const float*)d_in[19];
    const float* W_out = (const float*)d_in[20];
    const float* b_out = (const float*)d_in[21];
    float* out = (float*)d_out;
    const int B = in_sizes[0] / 784;

    precompute_wc<<<(784 * 64 + 64 + 255) / 256, 256>>>(W_in, b_in, W_tan, b_tan);

    cudaFuncSetAttribute(precompute_rot,
                         cudaFuncAttributeMaxDynamicSharedMemorySize, 3 * 4096 * 4);
    precompute_rot<<<2, 512, 3 * 4096 * 4>>>(A0, A1, t0_w1, t1_w1);

    cudaFuncSetAttribute(fused_kernel,
                         cudaFuncAttributeMaxDynamicSharedMemorySize, SMEM_FLOATS * 4);
    fused_kernel<<<(B + 127) / 128, 256, SMEM_FLOATS * 4>>>(
        x, s0, s1, s2,
        t0_w2, t0_b1, t0_b2,
        t1_w2, t1_b1, t1_b2,
        W_out, b_out, out, B);
}